// round 8
// baseline (speedup 1.0000x reference)
#include <cuda_runtime.h>
#include <cuda_bf16.h>
#include <cstdint>

// EmbeddingBagCollection: F=8 tables [N=200000, D=64] f32, values [F, T=163840] i32,
// offsets [F, B+1=8193] i32. Output [B=8192, F*D=512] f32.
//
// R8 = R5 (best, 74.2us) + register-budget fix:
//  - One warp per (f, b) bag; pair loading (half-warps take even/odd rows,
//    lane = float4 slot, 16 lanes x 16B = 256B row -> 2 rows per LDG.128).
//  - 64-index chunks: two coalesced index loads, then ONE predicated 32-pair
//    burst (96% of bags finish in a single burst, no mid-bag serialization).
//  - __launch_bounds__(256,3) -> 85 regs: ~16 float4 load destinations live
//    simultaneously, so the burst keeps ~16 LDG.128 (32 rows) in flight.
//  - shfl_xor(16) merges halves; lanes 0-15 store one coalesced 256B row
//    (unconditional -> empty bags write required zeros over the poison).

static constexpr int F = 8;
static constexpr int B = 8192;
static constexpr int N = 200000;
static constexpr int D = 64;
static constexpr int T = 163840;
static constexpr unsigned FULL = 0xffffffffu;

__global__ __launch_bounds__(256, 3)
void ebc_pool_kernel(const float* __restrict__ tables,
                     const int*   __restrict__ values,
                     const int*   __restrict__ offsets,
                     float*       __restrict__ out)
{
    const int gwarp = (blockIdx.x * blockDim.x + threadIdx.x) >> 5;
    const int lane  = threadIdx.x & 31;
    if (gwarp >= F * B) return;

    const int f = gwarp >> 13;          // B = 8192 = 2^13
    const int b = gwarp & (B - 1);

    const int half = lane >> 4;         // 0: even rows, 1: odd rows
    const int hl   = lane & 15;         // float4 slot within a row

    const int* __restrict__ offs = offsets + f * (B + 1);
    const int start = __ldg(offs + b);
    const int end   = __ldg(offs + b + 1);

    const int* __restrict__ vals = values + (size_t)f * T;
    const float4* __restrict__ tab4 =
        reinterpret_cast<const float4*>(tables + (size_t)f * N * D);  // 16 float4/row

    float4 acc = make_float4(0.f, 0.f, 0.f, 0.f);

    int i = start;
    while (i < end) {
        const int rem   = end - i;
        const int chunk = rem < 64 ? rem : 64;

        // Two coalesced index loads covering up to 64 positions (clamped lanes
        // stay in-bounds; idx1 may redundantly re-read position 0 — L1 hit).
        const int s0   = lane < chunk ? lane : 0;
        const int s1   = (lane + 32) < chunk ? (lane + 32) : 0;
        const int idx0 = __ldg(vals + i + s0);
        const int idx1 = __ldg(vals + i + s1);

        // Single predicated 32-pair burst: p<16 rows come from idx0, p>=16
        // from idx1 (rp = 2p+half < 32 iff p < 16). All loads issue together.
#pragma unroll
        for (int p = 0; p < 32; ++p) {
            const int rp = 2 * p + half;                 // row position in chunk
            const int r  = (p < 16) ? __shfl_sync(FULL, idx0, rp & 31)
                                    : __shfl_sync(FULL, idx1, rp & 31);
            if (rp < chunk) {
                const float4 v = __ldg(tab4 + (size_t)r * 16 + hl);
                acc.x += v.x; acc.y += v.y; acc.z += v.z; acc.w += v.w;
            }
        }
        i += chunk;
    }

    // Merge even/odd-row partial sums across half-warps.
    acc.x += __shfl_xor_sync(FULL, acc.x, 16);
    acc.y += __shfl_xor_sync(FULL, acc.y, 16);
    acc.z += __shfl_xor_sync(FULL, acc.z, 16);
    acc.w += __shfl_xor_sync(FULL, acc.w, 16);

    // Lanes 0-15 store one coalesced 256B row: out[b, f*D .. f*D+63].
    if (lane < 16) {
        float4* __restrict__ o =
            reinterpret_cast<float4*>(out + (size_t)b * (F * D) + f * D);
        o[hl] = acc;
    }
}

extern "C" void kernel_launch(void* const* d_in, const int* in_sizes, int n_in,
                              void* d_out, int out_size)
{
    const float* tables  = (const float*)d_in[0];  // [F, N, D]
    const int*   values  = (const int*)  d_in[1];  // [F, T]
    const int*   offsets = (const int*)  d_in[2];  // [F, B+1]
    float*       out     = (float*)d_out;          // [B, F*D]

    const int total_warps = F * B;                 // 65536 bags
    const int threads = 256;                       // 8 warps/block
    const int blocks = (total_warps * 32 + threads - 1) / threads;  // 8192

    ebc_pool_kernel<<<blocks, threads>>>(tables, values, offsets, out);
}

// round 9
// speedup vs baseline: 1.7466x; 1.7466x over previous
#include <cuda_runtime.h>
#include <cuda_bf16.h>
#include <cstdint>

// EmbeddingBagCollection: F=8 tables [N=200000, D=64] f32, values [F, T=163840] i32,
// offsets [F, B+1=8193] i32. Output [B=8192, F*D=512] f32.
//
// R9: cp.async (LDGSTS) gather — in-flight rows live in SMEM, not registers.
//  - One warp per (f, b) bag; 32-index chunks.
//  - Pair copies: half-warps take even/odd rows, lane = 16B slot
//    (16 lanes x 16B = 256B row) -> 2 rows per cp.async "instruction".
//    Up to 16 predicated cp.async.cg per chunk = 32 rows (8 KB) in flight
//    per warp with ~40 regs/thread (no register wall).
//  - Each thread reads back ONLY slots it wrote -> wait_group 0 is the only
//    sync needed (no __syncwarp).
//  - 128-thread blocks, 32 KB dynamic smem (8 KB/warp), <=48 KB so no opt-in.
//  - shfl_xor(16) merges halves; lanes 0-15 store one coalesced 256B row
//    (unconditional -> empty bags write required zeros over the poison).

static constexpr int F = 8;
static constexpr int B = 8192;
static constexpr int N = 200000;
static constexpr int D = 64;
static constexpr int T = 163840;
static constexpr unsigned FULL = 0xffffffffu;

static constexpr int WPB       = 4;               // warps per block
static constexpr int CHUNK     = 32;              // rows buffered per burst
static constexpr int ROW_BYTES = D * 4;           // 256
static constexpr int BUF_BYTES = CHUNK * ROW_BYTES;  // 8192 per warp

__global__ __launch_bounds__(WPB * 32)
void ebc_pool_kernel(const float* __restrict__ tables,
                     const int*   __restrict__ values,
                     const int*   __restrict__ offsets,
                     float*       __restrict__ out)
{
    extern __shared__ float4 sbuf[];              // [WPB][CHUNK][16] float4

    const int wib   = threadIdx.x >> 5;           // warp in block
    const int lane  = threadIdx.x & 31;
    const int gwarp = blockIdx.x * WPB + wib;     // grid sized exactly F*B

    const int f = gwarp >> 13;                    // B = 8192 = 2^13
    const int b = gwarp & (B - 1);

    const int half = lane >> 4;                   // 0: even rows, 1: odd rows
    const int hl   = lane & 15;                   // 16B slot within a row

    const int* __restrict__ offs = offsets + f * (B + 1);
    const int start = __ldg(offs + b);
    const int end   = __ldg(offs + b + 1);

    const int* __restrict__ vals = values + (size_t)f * T;
    const float4* __restrict__ tab4 =
        reinterpret_cast<const float4*>(tables + (size_t)f * N * D);  // 16 float4/row

    // Per-warp SMEM staging buffer.
    float4* __restrict__ bufg = sbuf + wib * (CHUNK * 16);
    const uint32_t buf_s =
        (uint32_t)__cvta_generic_to_shared(sbuf) + wib * BUF_BYTES;

    float4 acc = make_float4(0.f, 0.f, 0.f, 0.f);

    int i = start;
    while (i < end) {
        const int rem   = end - i;
        const int chunk = rem < CHUNK ? rem : CHUNK;

        // Coalesced index prefetch (clamped lanes stay in bounds).
        const int src = lane < chunk ? lane : 0;
        const int idx = __ldg(vals + i + src);

        // Burst: all needed pair-copies issue back-to-back into SMEM.
        // Thread (half, hl) copies bytes [hl*16, hl*16+16) of rows 2p+half.
#pragma unroll
        for (int p = 0; p < CHUNK / 2; ++p) {
            const int rp = 2 * p + half;          // row position in chunk
            const int r  = __shfl_sync(FULL, idx, rp & 31);
            if (rp < chunk) {
                const float4* g = tab4 + (size_t)r * 16 + hl;
                const uint32_t d = buf_s + rp * ROW_BYTES + hl * 16;
                asm volatile("cp.async.cg.shared.global [%0], [%1], 16;\n"
                             :: "r"(d), "l"(g) : "memory");
            }
        }
        asm volatile("cp.async.commit_group;\n" ::: "memory");
        asm volatile("cp.async.wait_group 0;\n" ::: "memory");

        // Accumulate from SMEM (each thread reads only slots it wrote).
#pragma unroll
        for (int p = 0; p < CHUNK / 2; ++p) {
            const int rp = 2 * p + half;
            if (rp < chunk) {
                const float4 v = bufg[rp * 16 + hl];
                acc.x += v.x; acc.y += v.y; acc.z += v.z; acc.w += v.w;
            }
        }
        i += chunk;
    }

    // Merge even/odd-row partial sums across half-warps.
    acc.x += __shfl_xor_sync(FULL, acc.x, 16);
    acc.y += __shfl_xor_sync(FULL, acc.y, 16);
    acc.z += __shfl_xor_sync(FULL, acc.z, 16);
    acc.w += __shfl_xor_sync(FULL, acc.w, 16);

    // Lanes 0-15 store one coalesced 256B row: out[b, f*D .. f*D+63].
    if (lane < 16) {
        float4* __restrict__ o =
            reinterpret_cast<float4*>(out + (size_t)b * (F * D) + f * D);
        o[hl] = acc;
    }
}

extern "C" void kernel_launch(void* const* d_in, const int* in_sizes, int n_in,
                              void* d_out, int out_size)
{
    const float* tables  = (const float*)d_in[0];  // [F, N, D]
    const int*   values  = (const int*)  d_in[1];  // [F, T]
    const int*   offsets = (const int*)  d_in[2];  // [F, B+1]
    float*       out     = (float*)d_out;          // [B, F*D]

    const int total_warps = F * B;                 // 65536 bags
    const int blocks  = total_warps / WPB;         // 16384
    const int threads = WPB * 32;                  // 128
    const int smem    = WPB * BUF_BYTES;           // 32 KB

    ebc_pool_kernel<<<blocks, threads, smem>>>(tables, values, offsets, out);
}